// round 14
// baseline (speedup 1.0000x reference)
#include <cuda_runtime.h>

// RadarNet R14: two kernels.
// K1: one warp per row (R13-proven, frozen).
// K2: 4 lane-groups/warp, TWO matrices per lane (ILP x2): each lane holds
//     column j of two independent S2 matrices; the Jacobi chain (shfl -> jrot
//     MUFU chain -> distribute -> FMA) dual-issues across the twin, hiding
//     latency that 3.5 warps/SMSP cannot. 4 sweeps (3 measured failing).

namespace {
constexpr int   TLEN = 512;
constexpr int   WINW = 20;
constexpr int   NW   = 493;
constexpr int   MAXB = 8192;
constexpr int   NSWEEP = 4;
}

__device__ float g_S2[MAXB * 64];

// ---------------------------------------------------------------------------
// Kernel 1: covariance + S2, one warp per row, 4 warps/block (frozen)
// ---------------------------------------------------------------------------
__global__ __launch_bounds__(128)
void radar_cov_kernel(const float* __restrict__ gx,
                      const float* __restrict__ gW1,
                      const float* __restrict__ gW2)
{
    __shared__ float W1s[320], W2s[128], Gs[160];
    __shared__ __align__(16) float xs[4][544];
    __shared__ float Cm[4][WINW][WINW + 1];
    __shared__ float Tgs[4][160];
    __shared__ float partS[4][8][22];
    __shared__ float lagS[4][24];
    __shared__ float mwS[4][WINW];

    const int tid = threadIdx.x, wp = tid >> 5, l = tid & 31;
    const int b = blockIdx.x * 4 + wp;
    const unsigned FULL = 0xffffffffu;

    {
        const float4* gx4 = reinterpret_cast<const float4*>(gx + b * TLEN);
        float4* xs4 = reinterpret_cast<float4*>(xs[wp]);
        #pragma unroll
        for (int q = 0; q < 4; ++q) xs4[l + 32 * q] = gx4[l + 32 * q];
        if (l < 8) xs4[128 + l] = make_float4(0.f, 0.f, 0.f, 0.f);
    }

    for (int i = tid; i < 320; i += 128) W1s[i] = gW1[i];
    if (tid < 128) W2s[tid] = gW2[tid];
    __syncthreads();
    for (int t = tid; t < 160; t += 128) {
        int w = t >> 3, c = t & 7;
        float s = 0.f;
        #pragma unroll
        for (int k = 0; k < 16; ++k) s = fmaf(W1s[w * 16 + k], W2s[k * 8 + c], s);
        Gs[t] = s;
    }
    __syncthreads();

    float xv[36];
    {
        const float4* base = reinterpret_cast<const float4*>(xs[wp] + 16 * l);
        #pragma unroll
        for (int q = 0; q < 9; ++q) {
            float4 t = base[q];
            xv[4*q+0] = t.x; xv[4*q+1] = t.y; xv[4*q+2] = t.z; xv[4*q+3] = t.w;
        }
    }
    float acc[21];
    #pragma unroll
    for (int d = 0; d < 21; ++d) acc[d] = 0.f;
    {
        const int nb = 16 * l;
        #pragma unroll
        for (int k = 0; k < 16; ++k) {
            if (nb + k < NW) {
                float xk = xv[k];
                #pragma unroll
                for (int d = 0; d < WINW; ++d) acc[d] = fmaf(xk, xv[k + d], acc[d]);
                acc[20] += xk;
            }
        }
    }
    #pragma unroll
    for (int d = 0; d < 21; ++d) {
        acc[d] += __shfl_down_sync(FULL, acc[d], 16);
        acc[d] += __shfl_down_sync(FULL, acc[d], 8);
    }
    if (l < 8) {
        #pragma unroll
        for (int d = 0; d < 21; ++d) partS[wp][l][d] = acc[d];
    }
    __syncwarp();
    if (l < 21) {
        float s = 0.f;
        #pragma unroll
        for (int k = 0; k < 8; ++k) s += partS[wp][k][l];
        lagS[wp][l] = s;
    }
    __syncwarp();

    {
        float sum0 = lagS[wp][20];
        float val = (l >= 1 && l < WINW) ? (xs[wp][NW - 1 + l] - xs[wp][l - 1]) : 0.f;
        #pragma unroll
        for (int o = 1; o < 32; o <<= 1) {
            float t = __shfl_up_sync(FULL, val, o);
            if (l >= o) val += t;
        }
        if (l < WINW) mwS[wp][l] = (sum0 + val) * (1.f / (float)NW);
    }
    __syncwarp();

    if (l < WINW) {
        const int d = l;
        const float inv = 1.f / (float)(NW - 1);
        float s = lagS[wp][d];
        {
            float cv = (s - (float)NW * mwS[wp][0] * mwS[wp][d]) * inv;
            Cm[wp][0][d] = cv; Cm[wp][d][0] = cv;
        }
        #pragma unroll
        for (int w = 1; w <= 19; ++w) {
            if (w + d < WINW) {
                s += xs[wp][NW - 1 + w] * xs[wp][NW - 1 + w + d]
                   - xs[wp][w - 1]      * xs[wp][w - 1 + d];
                float cv = (s - (float)NW * mwS[wp][w] * mwS[wp][w + d]) * inv;
                Cm[wp][w][w + d] = cv; Cm[wp][w + d][w] = cv;
            }
        }
    }
    __syncwarp();

    {
        const int wg = l >> 3, c = l & 7;
        float Gcol[WINW];
        #pragma unroll
        for (int v = 0; v < WINW; ++v) Gcol[v] = Gs[v * 8 + c];
        #pragma unroll
        for (int t = 0; t < 5; ++t) {
            const int w = wg + 4 * t;
            float s = 0.f;
            #pragma unroll
            for (int v = 0; v < WINW; ++v) s = fmaf(Cm[wp][w][v], Gcol[v], s);
            Tgs[wp][w * 8 + c] = s;
        }
    }
    __syncwarp();

    #pragma unroll
    for (int h = 0; h < 2; ++h) {
        const int e = l + 32 * h;
        const int a = e >> 3, c = e & 7;
        float s = 0.f;
        #pragma unroll
        for (int w = 0; w < WINW; ++w) s = fmaf(Gs[w * 8 + a], Tgs[wp][w * 8 + c], s);
        g_S2[b * 64 + e] = s;
    }
}

// ---------------------------------------------------------------------------
// Jacobi rotation
// ---------------------------------------------------------------------------
__device__ __forceinline__ void jrot(float app, float aqq, float apq,
                                     float& cc, float& ss, float& tt)
{
    float dn = 2.f * apq;
    dn += (dn >= 0.f ? 1e-38f : -1e-38f);
    float th = __fdividef(aqq - app, dn);
    th = fminf(fmaxf(th, -1e18f), 1e18f);
    tt = __fdividef(1.f, fabsf(th) + sqrtf(fmaf(th, th, 1.f)));
    if (th < 0.f) tt = -tt;
    cc = rsqrtf(fmaf(tt, tt, 1.f));
    ss = tt * cc;
}

// ---------------------------------------------------------------------------
// Kernel 2: 4 lane-groups/warp, 2 matrices per lane (ILP x2), 4 sweeps
// ---------------------------------------------------------------------------
__global__ __launch_bounds__(256)
void radar_eig_kernel(const float* __restrict__ gWl,
                      const float* __restrict__ gbl,
                      float* __restrict__ out, int B)
{
    __shared__ float wls[192];
    __shared__ float bls[3];

    const int tid = threadIdx.x, wp = tid >> 5, l = tid & 31;
    const int g = l >> 3, j = l & 7, gb = g << 3;
    const unsigned FULL = 0xffffffffu;

    for (int i = tid; i < 192; i += 256) wls[i] = gWl[i];
    if (tid < 3) bls[tid] = gbl[tid];
    __syncthreads();

    // warp handles 8 rows: groups hold rows (base+g) and (base+g+4)
    const int base = blockIdx.x * 64 + wp * 8;
    int rowA = base + g;
    int rowB = base + g + 4;
    if (rowA > B - 1) rowA = B - 1;
    if (rowB > B - 1) rowB = B - 1;

    float a[8], b2[8];
    {
        const float4* pa = reinterpret_cast<const float4*>(g_S2 + rowA * 64 + j * 8);
        float4 q0 = pa[0], q1 = pa[1];
        a[0]=q0.x; a[1]=q0.y; a[2]=q0.z; a[3]=q0.w;
        a[4]=q1.x; a[5]=q1.y; a[6]=q1.z; a[7]=q1.w;
        const float4* pb = reinterpret_cast<const float4*>(g_S2 + rowB * 64 + j * 8);
        float4 r0 = pb[0], r1 = pb[1];
        b2[0]=r0.x; b2[1]=r0.y; b2[2]=r0.z; b2[3]=r0.w;
        b2[4]=r1.x; b2[5]=r1.y; b2[6]=r1.z; b2[7]=r1.w;
    }
    float v[8], u[8];
    #pragma unroll
    for (int i = 0; i < 8; ++i) { v[i] = (i == j) ? 1.f : 0.f; u[i] = v[i]; }
    float dgA = a[j], dgB = b2[j];

    constexpr int P[7][4] = {{0,1,2,3},{0,2,3,4},{0,1,4,5},{0,2,1,6},
                             {0,3,2,1},{0,4,3,1},{0,5,1,2}};
    constexpr int Q[7][4] = {{7,6,5,4},{1,7,6,5},{2,3,7,6},{3,4,5,7},
                             {4,5,6,7},{5,6,7,2},{6,7,4,3}};
    constexpr unsigned PRT[7] = {
        (7u<<0)|(6u<<3)|(5u<<6)|(4u<<9)|(3u<<12)|(2u<<15)|(1u<<18)|(0u<<21),
        (1u<<0)|(0u<<3)|(7u<<6)|(6u<<9)|(5u<<12)|(4u<<15)|(3u<<18)|(2u<<21),
        (2u<<0)|(3u<<3)|(0u<<6)|(1u<<9)|(7u<<12)|(6u<<15)|(5u<<18)|(4u<<21),
        (3u<<0)|(5u<<3)|(4u<<6)|(0u<<9)|(2u<<12)|(1u<<15)|(7u<<18)|(6u<<21),
        (4u<<0)|(7u<<3)|(6u<<6)|(5u<<9)|(0u<<12)|(3u<<15)|(2u<<18)|(1u<<21),
        (5u<<0)|(2u<<3)|(1u<<6)|(7u<<9)|(6u<<12)|(0u<<15)|(4u<<18)|(3u<<21),
        (6u<<0)|(4u<<3)|(3u<<6)|(2u<<9)|(1u<<12)|(7u<<15)|(0u<<18)|(5u<<21)};

    #pragma unroll 1
    for (int sweep = 0; sweep < NSWEEP; ++sweep) {
        #pragma unroll
        for (int rr = 0; rr < 7; ++rr) {
            const int prt = (PRT[rr] >> (3 * j)) & 7;
            const bool isp = j < prt;
            const int src = gb + prt;

            // own-pair off-diagonal for both matrices (shared decode)
            float apairA = a[0], apairB = b2[0];
            #pragma unroll
            for (int i = 1; i < 8; ++i)
                if (prt == i) { apairA = a[i]; apairB = b2[i]; }
            float dgoA = __shfl_sync(FULL, dgA, src);
            float dgoB = __shfl_sync(FULL, dgB, src);
            float apoA = __shfl_sync(FULL, apairA, src);
            float apoB = __shfl_sync(FULL, apairB, src);
            float apqA = isp ? apoA : apairA;
            float apqB = isp ? apoB : apairB;
            float cA, sA, tA, cB, sB, tB;
            jrot(isp ? dgA : dgoA, isp ? dgoA : dgA, apqA, cA, sA, tA);
            jrot(isp ? dgB : dgoB, isp ? dgoB : dgB, apqB, cB, sB, tB);

            // distribute the 4 pair-rotations (both matrices)
            float ckA[4], skA[4], ckB[4], skB[4];
            #pragma unroll
            for (int k = 0; k < 4; ++k) {
                ckA[k] = __shfl_sync(FULL, cA, gb + P[rr][k]);
                skA[k] = __shfl_sync(FULL, sA, gb + P[rr][k]);
                ckB[k] = __shfl_sync(FULL, cB, gb + P[rr][k]);
                skB[k] = __shfl_sync(FULL, sB, gb + P[rr][k]);
            }

            // in-lane row updates (A <- J^T A) and V <- V J, both matrices
            #pragma unroll
            for (int k = 0; k < 4; ++k) {
                const int p = P[rr][k], q = Q[rr][k];
                float tp = a[p], tq = a[q];
                a[p] = fmaf(ckA[k], tp, -skA[k] * tq);
                a[q] = fmaf(skA[k], tp,  ckA[k] * tq);
                float vp = v[p], vq = v[q];
                v[p] = fmaf(ckA[k], vp, -skA[k] * vq);
                v[q] = fmaf(skA[k], vp,  ckA[k] * vq);
                float up2 = b2[p], uq2 = b2[q];
                b2[p] = fmaf(ckB[k], up2, -skB[k] * uq2);
                b2[q] = fmaf(skB[k], up2,  ckB[k] * uq2);
                float wp2 = u[p], wq2 = u[q];
                u[p] = fmaf(ckB[k], wp2, -skB[k] * wq2);
                u[q] = fmaf(skB[k], wp2,  ckB[k] * wq2);
            }

            // cross-lane column updates (A <- A J), own (c,s)
            float soA = isp ? -sA : sA;
            float soB = isp ? -sB : sB;
            #pragma unroll
            for (int i = 0; i < 8; ++i) {
                float oa = __shfl_sync(FULL, a[i], src);
                float ob = __shfl_sync(FULL, b2[i], src);
                a[i]  = fmaf(cA, a[i],  soA * oa);
                b2[i] = fmaf(cB, b2[i], soB * ob);
            }
            dgA = fmaf(isp ? -tA : tA, apqA, dgA);
            dgB = fmaf(isp ? -tB : tB, apqB, dgB);
        }
    }

    // transpose V,U (rows -> columns) within the 8-lane group
    #pragma unroll
    for (int m = 1; m < 8; m <<= 1) {
        #pragma unroll
        for (int i = 0; i < 8; ++i) {
            if (i & m) continue;
            const int ip = i | m;
            float sendV = (j & m) ? v[i] : v[ip];
            float recvV = __shfl_xor_sync(FULL, sendV, m);
            if (j & m) v[i] = recvV; else v[ip] = recvV;
            float sendU = (j & m) ? u[i] : u[ip];
            float recvU = __shfl_xor_sync(FULL, sendU, m);
            if (j & m) u[i] = recvU; else u[ip] = recvU;
        }
    }

    // head: out_t = sum_k log(l_k) * v_k^T M_t v_k  (both matrices)
    float lgA = __logf(fmaxf(dgA, 1e-30f));
    float lgB = __logf(fmaxf(dgB, 1e-30f));
    float qrA[3], qrB[3];
    #pragma unroll
    for (int t = 0; t < 3; ++t) {
        float accA = 0.f, accB = 0.f;
        #pragma unroll
        for (int i = 0; i < 8; ++i) {
            float wvA = 0.f, wvB = 0.f;
            #pragma unroll
            for (int jj = 0; jj < 8; ++jj) {
                float w = wls[t * 64 + i * 8 + jj];
                wvA = fmaf(w, v[jj], wvA);
                wvB = fmaf(w, u[jj], wvB);
            }
            accA = fmaf(v[i], wvA, accA);
            accB = fmaf(u[i], wvB, accB);
        }
        qrA[t] = accA * lgA;
        qrB[t] = accB * lgB;
    }
    #pragma unroll
    for (int t = 0; t < 3; ++t) {
        qrA[t] += __shfl_xor_sync(FULL, qrA[t], 1);
        qrA[t] += __shfl_xor_sync(FULL, qrA[t], 2);
        qrA[t] += __shfl_xor_sync(FULL, qrA[t], 4);
        qrB[t] += __shfl_xor_sync(FULL, qrB[t], 1);
        qrB[t] += __shfl_xor_sync(FULL, qrB[t], 2);
        qrB[t] += __shfl_xor_sync(FULL, qrB[t], 4);
    }
    if (j == 0) {
        out[rowA * 3 + 0] = qrA[0] + bls[0];
        out[rowA * 3 + 1] = qrA[1] + bls[1];
        out[rowA * 3 + 2] = qrA[2] + bls[2];
        out[rowB * 3 + 0] = qrB[0] + bls[0];
        out[rowB * 3 + 1] = qrB[1] + bls[1];
        out[rowB * 3 + 2] = qrB[2] + bls[2];
    }
}

extern "C" void kernel_launch(void* const* d_in, const int* in_sizes, int n_in,
                              void* d_out, int out_size)
{
    const float* x    = (const float*)d_in[0];
    const float* W1   = (const float*)d_in[1];
    const float* W2   = (const float*)d_in[2];
    const float* Wlin = (const float*)d_in[3];
    const float* blin = (const float*)d_in[4];
    float* out = (float*)d_out;

    const int B = in_sizes[0] / TLEN;     // 8192
    radar_cov_kernel<<<B / 4, 128>>>(x, W1, W2);
    radar_eig_kernel<<<(B + 63) / 64, 256>>>(Wlin, blin, out, B);
}